// round 11
// baseline (speedup 1.0000x reference)
#include <cuda_runtime.h>
#include <math.h>

#define ROWS 32768          // B*S
#define HD   768
#define KW   192            // HD/4 packed words
#define NTOT (ROWS*HD)

// ---------------- device scratch ----------------
__device__ int       g_acc[NTOT];          // int32 acc -> q22 int -> y_final int (reused)
__device__ unsigned  g_x8[ROWS*KW];
__device__ unsigned  g_r8[ROWS*KW];
__device__ unsigned  g_w8[HD*KW];
__device__ float     g_bscale[HD], g_bint[HD];
__device__ int       g_binti[HD];
__device__ long long g_Mbi[HD];
__device__ int       g_Ebi[HD];
__device__ long long g_M1i;
__device__ int       g_E1i;
__device__ int       g_biasint[HD];
__device__ float     g_sfout[HD];
__device__ long long g_M2i[HD];
__device__ int       g_E2i[HD];
__device__ float     g_s22, g_s8;
__device__ int       g_meani[ROWS];
__device__ unsigned  g_red[4];             // umin22,umax22,umin8,umax8
__device__ int       g_shift;

// order-preserving float<->uint key
__device__ __forceinline__ unsigned fkey(float f) {
    unsigned u = __float_as_uint(f);
    return (u & 0x80000000u) ? ~u : (u | 0x80000000u);
}
__device__ __forceinline__ float fdec(unsigned u) {
    return (u & 0x80000000u) ? __uint_as_float(u ^ 0x80000000u) : __uint_as_float(~u);
}

// round-half-even of t / 2^E  (E >= 1)
__device__ __forceinline__ long long rhe(long long t, int E) {
    long long q = t >> E;
    long long r = t - (q << E);
    long long half = 1LL << (E - 1);
    if (r > half)       q += 1;
    else if (r == half) q += (q & 1LL);
    return q;
}

// ---------------- K_init ----------------
__global__ void k_init() {
    g_red[0] = 0xFFFFFFFFu; g_red[1] = 0u;
    g_red[2] = 0xFFFFFFFFu; g_red[3] = 0u;
    g_shift = 0;
}

// ---------------- K_wq ----------------
__global__ __launch_bounds__(256) void k_wq(const float* __restrict__ w,
                                            const float* __restrict__ bias,
                                            const float* __restrict__ sact) {
    __shared__ float smn[256], smx[256];
    __shared__ float sscale;
    int row = blockIdx.x, t = threadIdx.x;
    float mn = 1e30f, mx = -1e30f;
    for (int i = t; i < HD; i += 256) {
        float v = w[row*HD + i];
        mn = fminf(mn, v); mx = fmaxf(mx, v);
    }
    smn[t] = mn; smx[t] = mx; __syncthreads();
    for (int s = 128; s > 0; s >>= 1) {
        if (t < s) { smn[t] = fminf(smn[t], smn[t+s]); smx[t] = fmaxf(smx[t], smx[t+s]); }
        __syncthreads();
    }
    if (t == 0) {
        float v = fmaxf(fmaxf(fabsf(smn[0]), fabsf(smx[0])), 1e-8f);
        float sc = v / 127.0f;
        sscale = sc;
        float bs = sc * sact[0];
        g_bscale[row] = bs;
        float bi = rintf(bias[row] / bs);
        bi = fminf(fmaxf(bi, -2147483647.0f), 2147483646.0f);
        g_bint[row] = bi;
        g_binti[row] = (int)bi;
    }
    __syncthreads();
    float sc = sscale;
    if (t < KW) {
        unsigned word = 0;
        #pragma unroll
        for (int b = 0; b < 4; b++) {
            float q = rintf(w[row*HD + 4*t + b] / sc);
            q = fminf(fmaxf(q, -127.0f), 126.0f);
            int qi = (int)q;
            word |= ((unsigned)(qi & 0xFF)) << (8*b);
        }
        g_w8[row*KW + t] = word;
    }
}

// ---------------- K_pack ----------------
__global__ __launch_bounds__(256) void k_pack(const float* __restrict__ hs, const float* __restrict__ s1p,
                                              const float* __restrict__ rs, const float* __restrict__ s2p) {
    int i = blockIdx.x * 256 + threadIdx.x;
    if (i >= ROWS*KW) return;
    float s1 = s1p[0], s2 = s2p[0];
    float4 hv = ((const float4*)hs)[i];
    float4 rv = ((const float4*)rs)[i];
    unsigned wa = 0, wb = 0;
    int q;
    q = __float2int_rn(hv.x/s1); wa |= (unsigned)(q & 0xFF);
    q = __float2int_rn(hv.y/s1); wa |= (unsigned)(q & 0xFF) << 8;
    q = __float2int_rn(hv.z/s1); wa |= (unsigned)(q & 0xFF) << 16;
    q = __float2int_rn(hv.w/s1); wa |= (unsigned)(q & 0xFF) << 24;
    q = __float2int_rn(rv.x/s2); wb |= (unsigned)(q & 0xFF);
    q = __float2int_rn(rv.y/s2); wb |= (unsigned)(q & 0xFF) << 8;
    q = __float2int_rn(rv.z/s2); wb |= (unsigned)(q & 0xFF) << 16;
    q = __float2int_rn(rv.w/s2); wb |= (unsigned)(q & 0xFF) << 24;
    g_x8[i] = wa; g_r8[i] = wb;
}

// ---------------- K_gemm: 128x128 tile, mma.sync m16n8k32 s8 tensor cores ----------------
// SMEM row pitch = 20 words (80B) for K-chunk of 64 bytes (16 words), stored in
// fragment-permuted order: within each 32-byte group, words [0,4,1,5,2,6,3,7].
// Thread lane l then reads {a0,a2} / {b0,b1} as one LDS.64 at word (kstep*8 + 2*(l&3)).
#define PITCH 20

__device__ __forceinline__ void imma16832(int* c, unsigned a0, unsigned a1, unsigned a2, unsigned a3,
                                          unsigned b0, unsigned b1) {
    asm volatile("mma.sync.aligned.m16n8k32.row.col.s32.s8.s8.s32 "
                 "{%0,%1,%2,%3}, {%4,%5,%6,%7}, {%8,%9}, {%0,%1,%2,%3};"
                 : "+r"(c[0]), "+r"(c[1]), "+r"(c[2]), "+r"(c[3])
                 : "r"(a0), "r"(a1), "r"(a2), "r"(a3), "r"(b0), "r"(b1));
}

__global__ __launch_bounds__(256, 2) void k_gemm(const float* __restrict__ insf) {
    __shared__ unsigned As[2][128*PITCH];
    __shared__ unsigned Bs[2][128*PITCH];
    __shared__ float sred[512];
    int tid = threadIdx.x;
    int lane = tid & 31, w = tid >> 5;
    int wm = w >> 2, wn = w & 3;            // warp tile: rows wm*64, cols wn*32
    int m0 = blockIdx.y * 128, n0 = blockIdx.x * 128;

    int acc[4][4][4];
    #pragma unroll
    for (int mf = 0; mf < 4; mf++)
        #pragma unroll
        for (int nf = 0; nf < 4; nf++)
            #pragma unroll
            for (int r = 0; r < 4; r++) acc[mf][nf][r] = 0;

    // loader: thread t handles row t>>1, 32-byte group g = t&1 (2 groups per 64B chunk)
    int lrow = tid >> 1, lg = tid & 1;
    const uint4* asrc = (const uint4*)&g_x8[(m0 + lrow)*KW + lg*8];
    const uint4* bsrc = (const uint4*)&g_w8[(n0 + lrow)*KW + lg*8];
    unsigned sbase = lrow*PITCH + lg*8;

    uint4 pa0 = asrc[0], pa1 = asrc[1];
    uint4 pb0 = bsrc[0], pb1 = bsrc[1];

    int fr = lane >> 2, fc = (lane & 3) * 2;   // fragment row-in-8, word-pair col

    for (int kt = 0; kt < 12; kt++) {
        int buf = kt & 1;
        unsigned* Ab = &As[buf][0];
        unsigned* Bb = &Bs[buf][0];
        // permuted store: v0 -> even slots, v1 -> odd slots
        Ab[sbase+0] = pa0.x; Ab[sbase+2] = pa0.y; Ab[sbase+4] = pa0.z; Ab[sbase+6] = pa0.w;
        Ab[sbase+1] = pa1.x; Ab[sbase+3] = pa1.y; Ab[sbase+5] = pa1.z; Ab[sbase+7] = pa1.w;
        Bb[sbase+0] = pb0.x; Bb[sbase+2] = pb0.y; Bb[sbase+4] = pb0.z; Bb[sbase+6] = pb0.w;
        Bb[sbase+1] = pb1.x; Bb[sbase+3] = pb1.y; Bb[sbase+5] = pb1.z; Bb[sbase+7] = pb1.w;
        __syncthreads();
        if (kt < 11) {
            pa0 = asrc[(kt+1)*4 + 0]; pa1 = asrc[(kt+1)*4 + 1];
            pb0 = bsrc[(kt+1)*4 + 0]; pb1 = bsrc[(kt+1)*4 + 1];
        }
        #pragma unroll
        for (int s = 0; s < 2; s++) {
            uint2 aA[4][2];
            #pragma unroll
            for (int mf = 0; mf < 4; mf++) {
                int r = wm*64 + mf*16 + fr;
                aA[mf][0] = *(const uint2*)&Ab[r*PITCH + s*8 + fc];
                aA[mf][1] = *(const uint2*)&Ab[(r+8)*PITCH + s*8 + fc];
            }
            uint2 bB[4];
            #pragma unroll
            for (int nf = 0; nf < 4; nf++) {
                int nr = wn*32 + nf*8 + fr;
                bB[nf] = *(const uint2*)&Bb[nr*PITCH + s*8 + fc];
            }
            #pragma unroll
            for (int mf = 0; mf < 4; mf++)
                #pragma unroll
                for (int nf = 0; nf < 4; nf++)
                    imma16832(acc[mf][nf], aA[mf][0].x, aA[mf][1].x, aA[mf][0].y, aA[mf][1].y,
                              bB[nf].x, bB[nf].y);
        }
        __syncthreads();
    }

    // epilogue: store acc, track min/max of x_act = (acc+b_int)*bscale + s_act*r
    float sa = insf[0];
    float bsv[4][2], biv[4][2];
    #pragma unroll
    for (int nf = 0; nf < 4; nf++) {
        int c = n0 + wn*32 + nf*8 + (lane & 3)*2;
        bsv[nf][0] = g_bscale[c];   bsv[nf][1] = g_bscale[c+1];
        biv[nf][0] = g_bint[c];     biv[nf][1] = g_bint[c+1];
    }
    float mnl = 1e30f, mxl = -1e30f;
    #pragma unroll
    for (int mf = 0; mf < 4; mf++) {
        #pragma unroll
        for (int half = 0; half < 2; half++) {
            int r = m0 + wm*64 + mf*16 + (lane >> 2) + half*8;
            const unsigned* rrow = &g_r8[r*KW];
            #pragma unroll
            for (int nf = 0; nf < 4; nf++) {
                int c = n0 + wn*32 + nf*8 + (lane & 3)*2;
                int a0 = acc[mf][nf][half*2 + 0];
                int a1 = acc[mf][nf][half*2 + 1];
                unsigned rw = rrow[c >> 2];
                int sh = (c & 3) * 8;
                int rb0 = (int)(signed char)(rw >> sh);
                int rb1 = (int)(signed char)(rw >> (sh + 8));
                float xa0 = ((float)a0 + biv[nf][0]) * bsv[nf][0] + sa * (float)rb0;
                float xa1 = ((float)a1 + biv[nf][1]) * bsv[nf][1] + sa * (float)rb1;
                mnl = fminf(mnl, fminf(xa0, xa1));
                mxl = fmaxf(mxl, fmaxf(xa0, xa1));
                *(int2*)&g_acc[r*HD + c] = make_int2(a0, a1);
            }
        }
    }
    sred[tid] = mnl; sred[256 + tid] = mxl; __syncthreads();
    for (int s = 128; s > 0; s >>= 1) {
        if (tid < s) {
            sred[tid] = fminf(sred[tid], sred[tid+s]);
            sred[256+tid] = fmaxf(sred[256+tid], sred[256+tid+s]);
        }
        __syncthreads();
    }
    if (tid == 0) {
        atomicMin(&g_red[0], fkey(sred[0]));
        atomicMax(&g_red[1], fkey(sred[256]));
    }
}

// ---------------- K_prep22 ----------------
__global__ __launch_bounds__(768) void k_prep22(const float* __restrict__ insf,
                                                const float* __restrict__ lnw,
                                                const float* __restrict__ lnb) {
    __shared__ float s22sh;
    int t = threadIdx.x;
    if (t == 0) {
        float mn = fdec(g_red[0]), mx = fdec(g_red[1]);
        float v = fmaxf(fmaxf(fabsf(mn), fabsf(mx)), 1e-8f);
        float s = v / 2097151.0f;
        g_s22 = s; s22sh = s;
    }
    __syncthreads();
    double z = (double)s22sh;
    {
        double d = (double)g_bscale[t] / z;
        int ex; double mant = frexp(d, &ex);
        g_Mbi[t] = (long long)floor(mant * 2147483648.0 + 0.5);
        g_Ebi[t] = 31 - ex;
    }
    if (t == 0) {
        double d = (double)insf[0] / z;
        int ex; double mant = frexp(d, &ex);
        g_M1i = (long long)floor(mant * 2147483648.0 + 0.5);
        g_E1i = 31 - ex;
    }
    float sf = sqrtf(768.0f) / 1073741824.0f;
    g_biasint[t] = (int)floorf((lnb[t] / lnw[t]) / sf);
    g_sfout[t]   = sf * lnw[t];
}

// ---------------- warp reduce helpers ----------------
__device__ __forceinline__ int wredAddI(int v) {
    #pragma unroll
    for (int o = 16; o > 0; o >>= 1) v += __shfl_down_sync(0xFFFFFFFFu, v, o);
    return v;
}
__device__ __forceinline__ long long wredAddLL(long long v) {
    #pragma unroll
    for (int o = 16; o > 0; o >>= 1) v += __shfl_down_sync(0xFFFFFFFFu, v, o);
    return v;
}
__device__ __forceinline__ float wredMinF(float v) {
    #pragma unroll
    for (int o = 16; o > 0; o >>= 1) v = fminf(v, __shfl_down_sync(0xFFFFFFFFu, v, o));
    return v;
}
__device__ __forceinline__ float wredMaxF(float v) {
    #pragma unroll
    for (int o = 16; o > 0; o >>= 1) v = fmaxf(v, __shfl_down_sync(0xFFFFFFFFu, v, o));
    return v;
}

// ---------------- K_ln1 ----------------
__global__ __launch_bounds__(256) void k_ln1() {
    __shared__ int  smi[8];
    __shared__ long long sml[8];
    __shared__ int  s_mean;
    int row = blockIdx.x, t = threadIdx.x;
    int base = row*HD;
    int p[3];
    int sum = 0;
    #pragma unroll
    for (int e = 0; e < 3; e++) {
        int c = t + e*256;
        int a = g_acc[base + c];
        long long zv = (long long)a + (long long)g_binti[c];
        long long p1 = rhe(zv * g_Mbi[c], g_Ebi[c]);
        unsigned rw = g_r8[row*KW + (c >> 2)];
        int rb = (int)(signed char)((rw >> ((c & 3)*8)) & 0xFF);
        long long p2 = rhe((long long)rb * g_M1i, g_E1i);
        long long pp = p1 + p2;
        pp = pp < -2097152LL ? -2097152LL : (pp > 2097151LL ? 2097151LL : pp);
        p[e] = (int)pp;
        g_acc[base + c] = (int)pp;
        sum += p[e];
    }
    int ws = wredAddI(sum);
    if ((t & 31) == 0) smi[t >> 5] = ws;
    __syncthreads();
    if (t == 0) {
        int tot = 0;
        #pragma unroll
        for (int i = 0; i < 8; i++) tot += smi[i];
        int mi = (int)rint((double)tot / 768.0);
        s_mean = mi;
        g_meani[row] = mi;
    }
    __syncthreads();
    int mi = s_mean;
    long long vs = 0;
    #pragma unroll
    for (int e = 0; e < 3; e++) {
        long long y = (long long)(p[e] - mi);
        vs += y*y;
    }
    long long wv = wredAddLL(vs);
    if ((t & 31) == 0) sml[t >> 5] = wv;
    __syncthreads();
    if (t == 0) {
        long long var0 = 0;
        #pragma unroll
        for (int i = 0; i < 8; i++) var0 += sml[i];
        double v = (double)var0; if (v < 1.0) v = 1.0;
        double sh = ceil(log2(sqrt(v / 4294967296.0)));
        atomicMax(&g_shift, (int)sh);
    }
}

// ---------------- K_ln2 ----------------
__global__ __launch_bounds__(256) void k_ln2() {
    __shared__ long long sml[8];
    __shared__ long long s_fac;
    __shared__ float smn[8], smx[8];
    int row = blockIdx.x, t = threadIdx.x;
    int base = row*HD;
    int shift = g_shift;
    int mi = g_meani[row];
    int y[3];
    long long vsum = 0;
    #pragma unroll
    for (int e = 0; e < 3; e++) {
        int c = t + e*256;
        int q = g_acc[base + c];
        y[e] = q - mi;
        long long ys = (long long)(y[e] >> shift);
        vsum += ys*ys;
    }
    long long wv = wredAddLL(vsum);
    if ((t & 31) == 0) sml[t >> 5] = wv;
    __syncthreads();
    if (t == 0) {
        long long var_int = 0;
        #pragma unroll
        for (int i = 0; i < 8; i++) var_int += sml[i];
        double stdv = floor(sqrt((double)var_int)) * exp2((double)shift);
        s_fac = (long long)floor(2147483648.0 / stdv);
    }
    __syncthreads();
    long long fac = s_fac;
    float mnl = 1e30f, mxl = -1e30f;
    #pragma unroll
    for (int e = 0; e < 3; e++) {
        int c = t + e*256;
        long long y2 = ((long long)y[e] * fac) >> 1;
        int yfin = (int)(y2 + (long long)g_biasint[c]);
        g_acc[base + c] = yfin;
        float outv = (float)yfin * g_sfout[c];
        mnl = fminf(mnl, outv); mxl = fmaxf(mxl, outv);
    }
    float wmn = wredMinF(mnl), wmx = wredMaxF(mxl);
    if ((t & 31) == 0) { smn[t >> 5] = wmn; smx[t >> 5] = wmx; }
    __syncthreads();
    if (t == 0) {
        float m0 = 1e30f, m1 = -1e30f;
        #pragma unroll
        for (int i = 0; i < 8; i++) { m0 = fminf(m0, smn[i]); m1 = fmaxf(m1, smx[i]); }
        atomicMin(&g_red[2], fkey(m0));
        atomicMax(&g_red[3], fkey(m1));
    }
}

// ---------------- K_prep8 ----------------
__global__ __launch_bounds__(768) void k_prep8(float* __restrict__ dout, int wscale) {
    __shared__ float s8sh;
    int t = threadIdx.x;
    if (t == 0) {
        float mn = fdec(g_red[2]), mx = fdec(g_red[3]);
        float v = fmaxf(fmaxf(fabsf(mn), fabsf(mx)), 1e-8f);
        float s = v / 127.0f;
        g_s8 = s; s8sh = s;
        if (wscale) dout[NTOT] = s;
    }
    __syncthreads();
    double d = (double)g_sfout[t] / (double)s8sh;
    int ex; double mant = frexp(d, &ex);
    g_M2i[t] = (long long)floor(mant * 2147483648.0 + 0.5);
    g_E2i[t] = 31 - ex;
}

// ---------------- K_final ----------------
__global__ __launch_bounds__(256) void k_final(float* __restrict__ dout) {
    int i = blockIdx.x * 256 + threadIdx.x;
    if (i >= NTOT/4) return;
    float s8 = g_s8;
    int4 v = ((const int4*)g_acc)[i];
    int c0 = (i * 4) % HD;
    int vv[4] = {v.x, v.y, v.z, v.w};
    float o[4];
    #pragma unroll
    for (int j = 0; j < 4; j++) {
        int c = c0 + j;
        long long tt = (long long)vv[j] * g_M2i[c];
        long long p = rhe(tt, g_E2i[c]);
        p = p < -128LL ? -128LL : (p > 127LL ? 127LL : p);
        o[j] = (float)p * s8;
    }
    ((float4*)dout)[i] = make_float4(o[0], o[1], o[2], o[3]);
}

// ---------------- launch ----------------
extern "C" void kernel_launch(void* const* d_in, const int* in_sizes, int n_in,
                              void* d_out, int out_size) {
    const float* hs   = (const float*)d_in[0];
    const float* hssf = (const float*)d_in[1];
    const float* inp  = (const float*)d_in[2];
    const float* insf = (const float*)d_in[3];
    const float* w    = (const float*)d_in[4];
    const float* bias = (const float*)d_in[5];
    const float* lnw  = (const float*)d_in[6];
    const float* lnb  = (const float*)d_in[7];
    float* dout = (float*)d_out;

    k_init<<<1, 1>>>();
    k_wq<<<HD, 256>>>(w, bias, hssf);
    k_pack<<<(ROWS*KW + 255)/256, 256>>>(hs, hssf, inp, insf);
    k_gemm<<<dim3(HD/128, ROWS/128), 256>>>(insf);
    k_prep22<<<1, 768>>>(insf, lnw, lnb);
    k_ln1<<<ROWS, 256>>>();
    k_ln2<<<ROWS, 256>>>();
    k_prep8<<<1, 768>>>(dout, out_size > NTOT ? 1 : 0);
    k_final<<<(NTOT/4 + 255)/256, 256>>>(dout);
}

// round 16
// speedup vs baseline: 1.0285x; 1.0285x over previous
#include <cuda_runtime.h>
#include <math.h>
#include <stdint.h>

#define ROWS 32768          // B*S
#define HD   768
#define KW   192            // HD/4 packed words
#define NTOT (ROWS*HD)

// ---------------- device scratch ----------------
__device__ int       g_acc[NTOT];          // int32 acc -> y_final int (reused)
__device__ unsigned  g_x8[ROWS*KW];
__device__ unsigned  g_r8[ROWS*KW];
__device__ unsigned  g_w8[HD*KW];
__device__ float     g_bscale[HD], g_bint[HD];
__device__ int       g_binti[HD];
__device__ long long g_Mbi[HD];
__device__ int       g_Ebi[HD];
__device__ long long g_M1i;
__device__ int       g_E1i;
__device__ int       g_biasint[HD];
__device__ float     g_sfout[HD];
__device__ long long g_M2i[HD];
__device__ int       g_E2i[HD];
__device__ float     g_s22, g_s8;
__device__ int       g_meani[ROWS];
__device__ unsigned  g_red[4];             // umin22,umax22,umin8,umax8
__device__ int       g_shift;

// order-preserving float<->uint key
__device__ __forceinline__ unsigned fkey(float f) {
    unsigned u = __float_as_uint(f);
    return (u & 0x80000000u) ? ~u : (u | 0x80000000u);
}
__device__ __forceinline__ float fdec(unsigned u) {
    return (u & 0x80000000u) ? __uint_as_float(u ^ 0x80000000u) : __uint_as_float(~u);
}

// round-half-even of t / 2^E  (E >= 1)
__device__ __forceinline__ long long rhe(long long t, int E) {
    long long q = t >> E;
    long long r = t - (q << E);
    long long half = 1LL << (E - 1);
    if (r > half)       q += 1;
    else if (r == half) q += (q & 1LL);
    return q;
}

// ---------------- warp reduce helpers ----------------
__device__ __forceinline__ int wredAddI(int v) {
    #pragma unroll
    for (int o = 16; o > 0; o >>= 1) v += __shfl_down_sync(0xFFFFFFFFu, v, o);
    return v;
}
__device__ __forceinline__ long long wredAddLL(long long v) {
    #pragma unroll
    for (int o = 16; o > 0; o >>= 1) v += __shfl_down_sync(0xFFFFFFFFu, v, o);
    return v;
}
__device__ __forceinline__ float wredMinF(float v) {
    #pragma unroll
    for (int o = 16; o > 0; o >>= 1) v = fminf(v, __shfl_down_sync(0xFFFFFFFFu, v, o));
    return v;
}
__device__ __forceinline__ float wredMaxF(float v) {
    #pragma unroll
    for (int o = 16; o > 0; o >>= 1) v = fmaxf(v, __shfl_down_sync(0xFFFFFFFFu, v, o));
    return v;
}

// ---------------- K_prep: fused init + weight-quant + activation pack ----------------
#define PACK_BLOCKS ((ROWS*KW)/256)   // 24576

__global__ __launch_bounds__(256) void k_prep(const float* __restrict__ w,
                                              const float* __restrict__ bias,
                                              const float* __restrict__ sact,
                                              const float* __restrict__ hs,
                                              const float* __restrict__ rs,
                                              const float* __restrict__ rsf) {
    int bid = blockIdx.x, t = threadIdx.x;
    if (bid < HD) {
        // ---- weight quantization path ----
        __shared__ float smn[256], smx[256];
        __shared__ float sscale;
        int row = bid;
        float mn = 1e30f, mx = -1e30f;
        for (int i = t; i < HD; i += 256) {
            float v = w[row*HD + i];
            mn = fminf(mn, v); mx = fmaxf(mx, v);
        }
        smn[t] = mn; smx[t] = mx; __syncthreads();
        for (int s = 128; s > 0; s >>= 1) {
            if (t < s) { smn[t] = fminf(smn[t], smn[t+s]); smx[t] = fmaxf(smx[t], smx[t+s]); }
            __syncthreads();
        }
        if (t == 0) {
            float v = fmaxf(fmaxf(fabsf(smn[0]), fabsf(smx[0])), 1e-8f);
            float sc = v / 127.0f;
            sscale = sc;
            float bs = sc * sact[0];
            g_bscale[row] = bs;
            float bi = rintf(bias[row] / bs);
            bi = fminf(fmaxf(bi, -2147483647.0f), 2147483646.0f);
            g_bint[row] = bi;
            g_binti[row] = (int)bi;
        }
        __syncthreads();
        float sc = sscale;
        if (t < KW) {
            unsigned word = 0;
            #pragma unroll
            for (int b = 0; b < 4; b++) {
                float q = rintf(w[row*HD + 4*t + b] / sc);
                q = fminf(fmaxf(q, -127.0f), 126.0f);
                int qi = (int)q;
                word |= ((unsigned)(qi & 0xFF)) << (8*b);
            }
            g_w8[row*KW + t] = word;
        }
    } else {
        // ---- activation pack path ----
        if (bid == HD && t == 0) {
            g_red[0] = 0xFFFFFFFFu; g_red[1] = 0u;
            g_red[2] = 0xFFFFFFFFu; g_red[3] = 0u;
            g_shift = 0;
        }
        int i = (bid - HD) * 256 + t;
        float s1 = sact[0], s2 = rsf[0];
        float4 hv = ((const float4*)hs)[i];
        float4 rv = ((const float4*)rs)[i];
        unsigned wa = 0, wb = 0;
        int q;
        q = __float2int_rn(hv.x/s1); wa |= (unsigned)(q & 0xFF);
        q = __float2int_rn(hv.y/s1); wa |= (unsigned)(q & 0xFF) << 8;
        q = __float2int_rn(hv.z/s1); wa |= (unsigned)(q & 0xFF) << 16;
        q = __float2int_rn(hv.w/s1); wa |= (unsigned)(q & 0xFF) << 24;
        q = __float2int_rn(rv.x/s2); wb |= (unsigned)(q & 0xFF);
        q = __float2int_rn(rv.y/s2); wb |= (unsigned)(q & 0xFF) << 8;
        q = __float2int_rn(rv.z/s2); wb |= (unsigned)(q & 0xFF) << 16;
        q = __float2int_rn(rv.w/s2); wb |= (unsigned)(q & 0xFF) << 24;
        g_x8[i] = wa; g_r8[i] = wb;
    }
}

// ---------------- K_gemm: 128x128 tile, mma.sync m16n8k32 s8 (proven R11 version) ----------------
#define PITCH 20

__device__ __forceinline__ void imma16832(int* c, unsigned a0, unsigned a1, unsigned a2, unsigned a3,
                                          unsigned b0, unsigned b1) {
    asm volatile("mma.sync.aligned.m16n8k32.row.col.s32.s8.s8.s32 "
                 "{%0,%1,%2,%3}, {%4,%5,%6,%7}, {%8,%9}, {%0,%1,%2,%3};"
                 : "+r"(c[0]), "+r"(c[1]), "+r"(c[2]), "+r"(c[3])
                 : "r"(a0), "r"(a1), "r"(a2), "r"(a3), "r"(b0), "r"(b1));
}

__global__ __launch_bounds__(256, 2) void k_gemm(const float* __restrict__ insf) {
    __shared__ unsigned As[2][128*PITCH];
    __shared__ unsigned Bs[2][128*PITCH];
    __shared__ float sred[512];
    int tid = threadIdx.x;
    int lane = tid & 31, w = tid >> 5;
    int wm = w >> 2, wn = w & 3;
    int m0 = blockIdx.y * 128, n0 = blockIdx.x * 128;

    int acc[4][4][4];
    #pragma unroll
    for (int mf = 0; mf < 4; mf++)
        #pragma unroll
        for (int nf = 0; nf < 4; nf++)
            #pragma unroll
            for (int r = 0; r < 4; r++) acc[mf][nf][r] = 0;

    int lrow = tid >> 1, lg = tid & 1;
    const uint4* asrc = (const uint4*)&g_x8[(m0 + lrow)*KW + lg*8];
    const uint4* bsrc = (const uint4*)&g_w8[(n0 + lrow)*KW + lg*8];
    unsigned sbase = lrow*PITCH + lg*8;

    uint4 pa0 = asrc[0], pa1 = asrc[1];
    uint4 pb0 = bsrc[0], pb1 = bsrc[1];

    int fr = lane >> 2, fc = (lane & 3) * 2;

    for (int kt = 0; kt < 12; kt++) {
        int buf = kt & 1;
        unsigned* Ab = &As[buf][0];
        unsigned* Bb = &Bs[buf][0];
        Ab[sbase+0] = pa0.x; Ab[sbase+2] = pa0.y; Ab[sbase+4] = pa0.z; Ab[sbase+6] = pa0.w;
        Ab[sbase+1] = pa1.x; Ab[sbase+3] = pa1.y; Ab[sbase+5] = pa1.z; Ab[sbase+7] = pa1.w;
        Bb[sbase+0] = pb0.x; Bb[sbase+2] = pb0.y; Bb[sbase+4] = pb0.z; Bb[sbase+6] = pb0.w;
        Bb[sbase+1] = pb1.x; Bb[sbase+3] = pb1.y; Bb[sbase+5] = pb1.z; Bb[sbase+7] = pb1.w;
        __syncthreads();
        if (kt < 11) {
            pa0 = asrc[(kt+1)*4 + 0]; pa1 = asrc[(kt+1)*4 + 1];
            pb0 = bsrc[(kt+1)*4 + 0]; pb1 = bsrc[(kt+1)*4 + 1];
        }
        #pragma unroll
        for (int s = 0; s < 2; s++) {
            uint2 aA[4][2];
            #pragma unroll
            for (int mf = 0; mf < 4; mf++) {
                int r = wm*64 + mf*16 + fr;
                aA[mf][0] = *(const uint2*)&Ab[r*PITCH + s*8 + fc];
                aA[mf][1] = *(const uint2*)&Ab[(r+8)*PITCH + s*8 + fc];
            }
            uint2 bB[4];
            #pragma unroll
            for (int nf = 0; nf < 4; nf++) {
                int nr = wn*32 + nf*8 + fr;
                bB[nf] = *(const uint2*)&Bb[nr*PITCH + s*8 + fc];
            }
            #pragma unroll
            for (int mf = 0; mf < 4; mf++)
                #pragma unroll
                for (int nf = 0; nf < 4; nf++)
                    imma16832(acc[mf][nf], aA[mf][0].x, aA[mf][1].x, aA[mf][0].y, aA[mf][1].y,
                              bB[nf].x, bB[nf].y);
        }
        __syncthreads();
    }

    float sa = insf[0];
    float bsv[4][2], biv[4][2];
    #pragma unroll
    for (int nf = 0; nf < 4; nf++) {
        int c = n0 + wn*32 + nf*8 + (lane & 3)*2;
        bsv[nf][0] = g_bscale[c];   bsv[nf][1] = g_bscale[c+1];
        biv[nf][0] = g_bint[c];     biv[nf][1] = g_bint[c+1];
    }
    float mnl = 1e30f, mxl = -1e30f;
    #pragma unroll
    for (int mf = 0; mf < 4; mf++) {
        #pragma unroll
        for (int half = 0; half < 2; half++) {
            int r = m0 + wm*64 + mf*16 + (lane >> 2) + half*8;
            const unsigned* rrow = &g_r8[r*KW];
            #pragma unroll
            for (int nf = 0; nf < 4; nf++) {
                int c = n0 + wn*32 + nf*8 + (lane & 3)*2;
                int a0 = acc[mf][nf][half*2 + 0];
                int a1 = acc[mf][nf][half*2 + 1];
                unsigned rw = rrow[c >> 2];
                int sh = (c & 3) * 8;
                int rb0 = (int)(signed char)(rw >> sh);
                int rb1 = (int)(signed char)(rw >> (sh + 8));
                float xa0 = ((float)a0 + biv[nf][0]) * bsv[nf][0] + sa * (float)rb0;
                float xa1 = ((float)a1 + biv[nf][1]) * bsv[nf][1] + sa * (float)rb1;
                mnl = fminf(mnl, fminf(xa0, xa1));
                mxl = fmaxf(mxl, fmaxf(xa0, xa1));
                *(int2*)&g_acc[r*HD + c] = make_int2(a0, a1);
            }
        }
    }
    sred[tid] = mnl; sred[256 + tid] = mxl; __syncthreads();
    for (int s = 128; s > 0; s >>= 1) {
        if (tid < s) {
            sred[tid] = fminf(sred[tid], sred[tid+s]);
            sred[256+tid] = fmaxf(sred[256+tid], sred[256+tid+s]);
        }
        __syncthreads();
    }
    if (tid == 0) {
        atomicMin(&g_red[0], fkey(sred[0]));
        atomicMax(&g_red[1], fkey(sred[256]));
    }
}

// ---------------- K_prep22 ----------------
__global__ __launch_bounds__(768) void k_prep22(const float* __restrict__ insf,
                                                const float* __restrict__ lnw,
                                                const float* __restrict__ lnb) {
    __shared__ float s22sh;
    int t = threadIdx.x;
    if (t == 0) {
        float mn = fdec(g_red[0]), mx = fdec(g_red[1]);
        float v = fmaxf(fmaxf(fabsf(mn), fabsf(mx)), 1e-8f);
        float s = v / 2097151.0f;
        g_s22 = s; s22sh = s;
    }
    __syncthreads();
    double z = (double)s22sh;
    {
        double d = (double)g_bscale[t] / z;
        int ex; double mant = frexp(d, &ex);
        g_Mbi[t] = (long long)floor(mant * 2147483648.0 + 0.5);
        g_Ebi[t] = 31 - ex;
    }
    if (t == 0) {
        double d = (double)insf[0] / z;
        int ex; double mant = frexp(d, &ex);
        g_M1i = (long long)floor(mant * 2147483648.0 + 0.5);
        g_E1i = 31 - ex;
    }
    float sf = sqrtf(768.0f) / 1073741824.0f;
    g_biasint[t] = (int)floorf((lnb[t] / lnw[t]) / sf);
    g_sfout[t]   = sf * lnw[t];
}

// ---------------- q22 recompute helper (shared by ln1/ln2) ----------------
// Computes the 24 q22 values for one lane's chunk of a row.
__device__ __forceinline__ void q22_row_chunk(int row, int c0,
                                              const int* __restrict__ sh_binti,
                                              const long long* __restrict__ sh_Mbi,
                                              const int* __restrict__ sh_Ebi,
                                              long long M1, int E1,
                                              int* __restrict__ p) {
    const int4* ap = (const int4*)&g_acc[row*HD + c0];
    int4 av[6];
    #pragma unroll
    for (int j = 0; j < 6; j++) av[j] = ap[j];
    const uint2* rp = (const uint2*)&g_r8[row*KW + (c0 >> 2)];
    uint2 ru[3];
    #pragma unroll
    for (int j = 0; j < 3; j++) ru[j] = rp[j];
    unsigned rw[6] = { ru[0].x, ru[0].y, ru[1].x, ru[1].y, ru[2].x, ru[2].y };
    const int* a = (const int*)av;
    #pragma unroll
    for (int j = 0; j < 24; j++) {
        int c = c0 + j;
        long long zv = (long long)a[j] + (long long)sh_binti[c];
        long long p1 = rhe(zv * sh_Mbi[c], sh_Ebi[c]);
        int rb = (int)(signed char)((rw[j >> 2] >> ((j & 3)*8)) & 0xFF);
        long long p2 = rhe((long long)rb * M1, E1);
        long long pp = p1 + p2;
        pp = pp < -2097152LL ? -2097152LL : (pp > 2097151LL ? 2097151LL : pp);
        p[j] = (int)pp;
    }
}

// ---------------- K_ln1: warp-per-row, q22 + mean + var0 + global shift ----------------
__global__ __launch_bounds__(256) void k_ln1() {
    __shared__ int       sh_binti[HD];
    __shared__ long long sh_Mbi[HD];
    __shared__ int       sh_Ebi[HD];
    int t = threadIdx.x;
    #pragma unroll
    for (int e = 0; e < 3; e++) {
        int c = t + e*256;
        sh_binti[c] = g_binti[c];
        sh_Mbi[c]   = g_Mbi[c];
        sh_Ebi[c]   = g_Ebi[c];
    }
    __syncthreads();
    long long M1 = g_M1i; int E1 = g_E1i;

    int w = t >> 5, lane = t & 31;
    int row = blockIdx.x * 8 + w;
    int c0 = lane * 24;

    int p[24];
    q22_row_chunk(row, c0, sh_binti, sh_Mbi, sh_Ebi, M1, E1, p);

    int sum = 0;
    #pragma unroll
    for (int j = 0; j < 24; j++) sum += p[j];
    sum = wredAddI(sum);
    int mi;
    if (lane == 0) {
        mi = (int)rint((double)sum / 768.0);
        g_meani[row] = mi;
    }
    mi = __shfl_sync(0xFFFFFFFFu, mi, 0);

    long long vs = 0;
    #pragma unroll
    for (int j = 0; j < 24; j++) {
        long long y = (long long)(p[j] - mi);
        vs += y*y;
    }
    vs = wredAddLL(vs);
    if (lane == 0) {
        double v = (double)vs; if (v < 1.0) v = 1.0;
        double sh = ceil(log2(sqrt(v / 4294967296.0)));
        atomicMax(&g_shift, (int)sh);
    }
}

// ---------------- K_ln2: warp-per-row, recompute q22 + normalize + out min/max ----------------
__global__ __launch_bounds__(256) void k_ln2() {
    __shared__ int       sh_binti[HD];
    __shared__ long long sh_Mbi[HD];
    __shared__ int       sh_Ebi[HD];
    __shared__ int       sh_biasint[HD];
    __shared__ float     sh_sfout[HD];
    __shared__ float smn[8], smx[8];
    int t = threadIdx.x;
    #pragma unroll
    for (int e = 0; e < 3; e++) {
        int c = t + e*256;
        sh_binti[c]   = g_binti[c];
        sh_Mbi[c]     = g_Mbi[c];
        sh_Ebi[c]     = g_Ebi[c];
        sh_biasint[c] = g_biasint[c];
        sh_sfout[c]   = g_sfout[c];
    }
    __syncthreads();
    long long M1 = g_M1i; int E1 = g_E1i;
    int shift = g_shift;

    int w = t >> 5, lane = t & 31;
    int row = blockIdx.x * 8 + w;
    int c0 = lane * 24;
    int mi = g_meani[row];

    int p[24];
    q22_row_chunk(row, c0, sh_binti, sh_Mbi, sh_Ebi, M1, E1, p);

    long long vsum = 0;
    #pragma unroll
    for (int j = 0; j < 24; j++) {
        int y = p[j] - mi;
        long long ys = (long long)(y >> shift);
        vsum += ys*ys;
    }
    vsum = wredAddLL(vsum);
    long long fac;
    if (lane == 0) {
        double stdv = floor(sqrt((double)vsum)) * exp2((double)shift);
        fac = (long long)floor(2147483648.0 / stdv);
    }
    fac = __shfl_sync(0xFFFFFFFFu, fac, 0);

    int yo[24];
    float mnl = 1e30f, mxl = -1e30f;
    #pragma unroll
    for (int j = 0; j < 24; j++) {
        int c = c0 + j;
        int y = p[j] - mi;
        long long y2 = ((long long)y * fac) >> 1;
        int yfin = (int)(y2 + (long long)sh_biasint[c]);
        yo[j] = yfin;
        float outv = (float)yfin * sh_sfout[c];
        mnl = fminf(mnl, outv); mxl = fmaxf(mxl, outv);
    }
    int4* dst = (int4*)&g_acc[row*HD + c0];
    #pragma unroll
    for (int j = 0; j < 6; j++)
        dst[j] = make_int4(yo[4*j], yo[4*j+1], yo[4*j+2], yo[4*j+3]);

    mnl = wredMinF(mnl); mxl = wredMaxF(mxl);
    if (lane == 0) { smn[w] = mnl; smx[w] = mxl; }
    __syncthreads();
    if (t == 0) {
        float m0 = 1e30f, m1 = -1e30f;
        #pragma unroll
        for (int i = 0; i < 8; i++) { m0 = fminf(m0, smn[i]); m1 = fmaxf(m1, smx[i]); }
        atomicMin(&g_red[2], fkey(m0));
        atomicMax(&g_red[3], fkey(m1));
    }
}

// ---------------- K_prep8 ----------------
__global__ __launch_bounds__(768) void k_prep8(float* __restrict__ dout, int wscale) {
    __shared__ float s8sh;
    int t = threadIdx.x;
    if (t == 0) {
        float mn = fdec(g_red[2]), mx = fdec(g_red[3]);
        float v = fmaxf(fmaxf(fabsf(mn), fabsf(mx)), 1e-8f);
        float s = v / 127.0f;
        g_s8 = s; s8sh = s;
        if (wscale) dout[NTOT] = s;
    }
    __syncthreads();
    double d = (double)g_sfout[t] / (double)s8sh;
    int ex; double mant = frexp(d, &ex);
    g_M2i[t] = (long long)floor(mant * 2147483648.0 + 0.5);
    g_E2i[t] = 31 - ex;
}

// ---------------- K_final: integer 8-bit requantization ----------------
__global__ __launch_bounds__(256) void k_final(float* __restrict__ dout) {
    int i = blockIdx.x * 256 + threadIdx.x;
    if (i >= NTOT/4) return;
    float s8 = g_s8;
    int4 v = ((const int4*)g_acc)[i];
    int c0 = (i * 4) % HD;
    int vv[4] = {v.x, v.y, v.z, v.w};
    float o[4];
    #pragma unroll
    for (int j = 0; j < 4; j++) {
        int c = c0 + j;
        long long tt = (long long)vv[j] * g_M2i[c];
        long long p = rhe(tt, g_E2i[c]);
        p = p < -128LL ? -128LL : (p > 127LL ? 127LL : p);
        o[j] = (float)p * s8;
    }
    ((float4*)dout)[i] = make_float4(o[0], o[1], o[2], o[3]);
}

// ---------------- launch ----------------
extern "C" void kernel_launch(void* const* d_in, const int* in_sizes, int n_in,
                              void* d_out, int out_size) {
    const float* hs   = (const float*)d_in[0];
    const float* hssf = (const float*)d_in[1];
    const float* inp  = (const float*)d_in[2];
    const float* insf = (const float*)d_in[3];
    const float* w    = (const float*)d_in[4];
    const float* bias = (const float*)d_in[5];
    const float* lnw  = (const float*)d_in[6];
    const float* lnb  = (const float*)d_in[7];
    float* dout = (float*)d_out;

    k_prep<<<HD + PACK_BLOCKS, 256>>>(w, bias, hssf, hs, inp, insf);
    k_gemm<<<dim3(HD/128, ROWS/128), 256>>>(insf);
    k_prep22<<<1, 768>>>(insf, lnw, lnb);
    k_ln1<<<ROWS/8, 256>>>();
    k_ln2<<<ROWS/8, 256>>>();
    k_prep8<<<1, 768>>>(dout, out_size > NTOT ? 1 : 0);
    k_final<<<(NTOT/4 + 255)/256, 256>>>(dout);
}